// round 2
// baseline (speedup 1.0000x reference)
#include <cuda_runtime.h>
#include <cuda_bf16.h>

#define N_NODES 100000
#define N_EDGES 1600000
#define IN_DIM  128
#define HID     256
#define OUT_DIM 128

// ---------------- scratch (no allocations allowed) ----------------
static __device__ float  g_aggr[(size_t)N_NODES * IN_DIM];   // 51.2 MB
static __device__ float  g_h1[(size_t)N_NODES * HID];        // 102.4 MB
static __device__ double g_sum1[HID], g_sq1[HID];
static __device__ double g_sum2[OUT_DIM], g_sq2[OUT_DIM];
static __device__ float  g_scale1[HID], g_shift1[HID];
static __device__ float  g_scale2[OUT_DIM], g_shift2[OUT_DIM];

// ---------------- init: aggr = (1+eps)*x ; zero stat accumulators ----------------
__global__ void init_kernel(const float4* __restrict__ x4, const float* __restrict__ eps) {
    int i = blockIdx.x * 256 + threadIdx.x;           // 3.2M float4 exactly
    float s = 1.0f + eps[0];
    float4 v = x4[i];
    v.x *= s; v.y *= s; v.z *= s; v.w *= s;
    ((float4*)g_aggr)[i] = v;
    if (blockIdx.x == 0) {
        int t = threadIdx.x;
        g_sum1[t] = 0.0; g_sq1[t] = 0.0;
        if (t < OUT_DIM) { g_sum2[t] = 0.0; g_sq2[t] = 0.0; }
    }
}

// ---------------- scatter: aggr[dst] += x[src], one warp per edge ----------------
__global__ void scatter_kernel(const float4* __restrict__ x4, const int* __restrict__ ei) {
    int w    = (blockIdx.x * 256 + threadIdx.x) >> 5;   // edge id (grid sized exactly)
    int lane = threadIdx.x & 31;
    int s = __ldg(ei + w);
    int d = __ldg(ei + N_EDGES + w);
    float4 v = __ldg(x4 + (size_t)s * 32 + lane);
    float* p = g_aggr + (size_t)d * IN_DIM + lane * 4;
    asm volatile("red.global.add.v4.f32 [%0], {%1,%2,%3,%4};"
                 :: "l"(p), "f"(v.x), "f"(v.y), "f"(v.z), "f"(v.w) : "memory");
}

// ---------------- tiled fp32 GEMM with fused BN(A) and fused column stats ----------------
// Tile: 128 rows x 64 cols, 256 threads, 8x4 register blocking, K chunked by 128.
template<int LDA, int NTOT, int KTOT, bool FUSE_BN_A>
__device__ __forceinline__ void gemm_impl(
    const float* __restrict__ A, const float* __restrict__ W,
    const float* __restrict__ bias,
    const float* __restrict__ scA, const float* __restrict__ shA,
    float* __restrict__ out, double* __restrict__ stS, double* __restrict__ stQ, int M)
{
    extern __shared__ float sm[];
    float* As   = sm;                 // 128 * 132
    float* Bst  = sm + 128 * 132;     // 64  * 132  (B transposed: [c][k])
    float* s_sum = Bst + 64 * 132;    // 64
    float* s_sq  = s_sum + 64;        // 64

    const int tid = threadIdx.x;
    const int tx = tid & 15, ty = tid >> 4;
    const int m0 = blockIdx.x * 128;
    const int n0 = blockIdx.y * 64;

    if (tid < 64) { s_sum[tid] = 0.f; s_sq[tid] = 0.f; }

    float acc[8][4];
    #pragma unroll
    for (int i = 0; i < 8; i++)
        #pragma unroll
        for (int j = 0; j < 4; j++) acc[i][j] = 0.f;

    for (int kk = 0; kk < KTOT; kk += 128) {
        // A tile: 128x128 floats, coalesced float4 loads
        #pragma unroll
        for (int i = 0; i < 16; i++) {
            int idx = tid + 256 * i;
            int r   = idx >> 5;
            int c4  = (idx & 31) << 2;
            int gm  = m0 + r;
            float4 v = make_float4(0.f, 0.f, 0.f, 0.f);
            if (gm < M) {
                v = *(const float4*)(A + (size_t)gm * LDA + kk + c4);
                if (FUSE_BN_A) {
                    float4 sc = *(const float4*)(scA + kk + c4);
                    float4 sh = *(const float4*)(shA + kk + c4);
                    v.x = fmaxf(fmaf(v.x, sc.x, sh.x), 0.f);
                    v.y = fmaxf(fmaf(v.y, sc.y, sh.y), 0.f);
                    v.z = fmaxf(fmaf(v.z, sc.z, sh.z), 0.f);
                    v.w = fmaxf(fmaf(v.w, sc.w, sh.w), 0.f);
                }
            }
            *(float4*)(As + r * 132 + c4) = v;
        }
        // B tile transposed into smem: Bst[c][k] = W[kk+k][n0+c]
        #pragma unroll
        for (int i = 0; i < 32; i++) {
            int idx = tid + 256 * i;
            int k = idx >> 6;
            int c = idx & 63;
            Bst[c * 132 + k] = W[(size_t)(kk + k) * NTOT + n0 + c];
        }
        __syncthreads();

        #pragma unroll 4
        for (int k = 0; k < 128; k += 4) {
            float4 b4[4];
            #pragma unroll
            for (int j = 0; j < 4; j++)
                b4[j] = *(const float4*)(Bst + (tx + 16 * j) * 132 + k);
            #pragma unroll
            for (int i = 0; i < 8; i++) {
                float4 a = *(const float4*)(As + (ty + 16 * i) * 132 + k);
                #pragma unroll
                for (int j = 0; j < 4; j++) {
                    acc[i][j] = fmaf(a.x, b4[j].x, acc[i][j]);
                    acc[i][j] = fmaf(a.y, b4[j].y, acc[i][j]);
                    acc[i][j] = fmaf(a.z, b4[j].z, acc[i][j]);
                    acc[i][j] = fmaf(a.w, b4[j].w, acc[i][j]);
                }
            }
        }
        __syncthreads();
    }

    // epilogue: +bias, write, accumulate column sum / sumsq
    #pragma unroll
    for (int j = 0; j < 4; j++) {
        int c = n0 + tx + 16 * j;
        float bia = bias[c];
        float cs = 0.f, cq = 0.f;
        #pragma unroll
        for (int i = 0; i < 8; i++) {
            int gm = m0 + ty + 16 * i;
            if (gm < M) {
                float v = acc[i][j] + bia;
                out[(size_t)gm * NTOT + c] = v;
                cs += v; cq += v * v;
            }
        }
        atomicAdd(&s_sum[tx + 16 * j], cs);
        atomicAdd(&s_sq[tx + 16 * j], cq);
    }
    __syncthreads();
    if (tid < 64) {
        atomicAdd(&stS[n0 + tid], (double)s_sum[tid]);
        atomicAdd(&stQ[n0 + tid], (double)s_sq[tid]);
    }
}

__global__ void __launch_bounds__(256, 2)
gemm1_kernel(const float* __restrict__ W1, const float* __restrict__ b1, int M) {
    gemm_impl<IN_DIM, HID, IN_DIM, false>(g_aggr, W1, b1, nullptr, nullptr,
                                          g_h1, g_sum1, g_sq1, M);
}

__global__ void __launch_bounds__(256, 2)
gemm2_kernel(const float* __restrict__ W2, const float* __restrict__ b2,
             float* __restrict__ out, int M) {
    gemm_impl<HID, OUT_DIM, HID, true>(g_h1, W2, b2, g_scale1, g_shift1,
                                       out, g_sum2, g_sq2, M);
}

// ---------------- BN stats -> scale/shift ----------------
__global__ void stats1_kernel(const float* __restrict__ g, const float* __restrict__ b) {
    int c = threadIdx.x;  // 256
    double invN = 1.0 / (double)N_NODES;
    double mu  = g_sum1[c] * invN;
    double var = g_sq1[c] * invN - mu * mu;
    float rstd = rsqrtf((float)var + 1e-5f);
    float sc = g[c] * rstd;
    g_scale1[c] = sc;
    g_shift1[c] = b[c] - (float)mu * sc;
}

__global__ void stats2_kernel(const float* __restrict__ g, const float* __restrict__ b) {
    int c = threadIdx.x;  // 128
    double invN = 1.0 / (double)N_NODES;
    double mu  = g_sum2[c] * invN;
    double var = g_sq2[c] * invN - mu * mu;
    float rstd = rsqrtf((float)var + 1e-5f);
    float sc = g[c] * rstd;
    g_scale2[c] = sc;
    g_shift2[c] = b[c] - (float)mu * sc;
}

// ---------------- final: out = relu(out*scale2 + shift2) in place ----------------
__global__ void final_kernel(float4* __restrict__ out4) {
    int i = blockIdx.x * 256 + threadIdx.x;   // 3.2M float4 exactly
    float4 v = out4[i];
    int c4 = i & 31;                          // 128 cols = 32 float4 per row
    float4 sc = ((const float4*)g_scale2)[c4];
    float4 sh = ((const float4*)g_shift2)[c4];
    v.x = fmaxf(fmaf(v.x, sc.x, sh.x), 0.f);
    v.y = fmaxf(fmaf(v.y, sc.y, sh.y), 0.f);
    v.z = fmaxf(fmaf(v.z, sc.z, sh.z), 0.f);
    v.w = fmaxf(fmaf(v.w, sc.w, sh.w), 0.f);
    out4[i] = v;
}

// ---------------- launch ----------------
extern "C" void kernel_launch(void* const* d_in, const int* in_sizes, int n_in,
                              void* d_out, int out_size) {
    const float* x     = (const float*)d_in[0];
    const int*   ei    = (const int*)  d_in[1];
    const float* eps   = (const float*)d_in[2];
    const float* W1    = (const float*)d_in[3];
    const float* b1    = (const float*)d_in[4];
    const float* g1    = (const float*)d_in[5];
    const float* beta1 = (const float*)d_in[6];
    const float* W2    = (const float*)d_in[7];
    const float* b2    = (const float*)d_in[8];
    const float* g2    = (const float*)d_in[9];
    const float* beta2 = (const float*)d_in[10];
    float* out = (float*)d_out;

    const int SMEM_BYTES = (128 * 132 + 64 * 132 + 128) * 4;  // 101888
    cudaFuncSetAttribute(gemm1_kernel, cudaFuncAttributeMaxDynamicSharedMemorySize, SMEM_BYTES);
    cudaFuncSetAttribute(gemm2_kernel, cudaFuncAttributeMaxDynamicSharedMemorySize, SMEM_BYTES);

    // 12.8M floats = 3.2M float4 -> 12500 blocks of 256
    init_kernel<<<12500, 256>>>((const float4*)x, eps);
    // 1.6M edges, 8 warps/block -> 200000 blocks
    scatter_kernel<<<200000, 256>>>((const float4*)x, ei);

    dim3 g1d((N_NODES + 127) / 128, HID / 64);      // 782 x 4
    gemm1_kernel<<<g1d, 256, SMEM_BYTES>>>(W1, b1, N_NODES);
    stats1_kernel<<<1, HID>>>(g1, beta1);

    dim3 g2d((N_NODES + 127) / 128, OUT_DIM / 64);  // 782 x 2
    gemm2_kernel<<<g2d, 256, SMEM_BYTES>>>(W2, b2, out, N_NODES);
    stats2_kernel<<<1, OUT_DIM>>>(g2, beta2);

    final_kernel<<<12500, 256>>>((float4*)out);
}